// round 9
// baseline (speedup 1.0000x reference)
#include <cuda_runtime.h>

// KAN 3x3 convolution — fully polynomialized form, occupancy-tuned.
// x: (32, 256, 256) f32 in [0,1), base_weight: (3,3), spline_weight: (3,3,8)
// out: (32, 254, 254) f32
//
// spline_p(x) + silu(x)*bw_p collapses (for x in [0,1), silu ~ Chebyshev
// cubic, abs err ~1.3e-4) to:  c1'x + c2'x^2 + c3'x^3 + d1 R1 + d2 R2
// with R_k = relu(x - knot_k)^3, and all constants folded into one C*.
//
// Round-9 change: per-thread tile 4x4 -> 2x4 (8 accumulators) and
// __launch_bounds__(256,3). Cuts live registers below the 85-reg cap so the
// 45 folded coefficients stay in registers (no spill LDL/STL), and raises
// occupancy from ~21% to ~37% to hide FFMA latency.

namespace {
constexpr int H  = 256, W  = 256;
constexpr int Ho = 254, Wo = 254;
constexpr int NB = 8;          // GRID_SIZE + SPLINE_ORDER
constexpr int TW = 4, TH = 2;  // per-thread output tile
constexpr int BTX = 32, BTY = 8;  // 256 threads; block covers 128x16 outputs

// Chebyshev cubic fit of silu on [0,1]
constexpr float Q0 = 0.0001204f;
constexpr float Q1 = 0.496111f;
constexpr float Q2 = 0.270337f;
constexpr float Q3 = -0.035467f;
}

__global__ __launch_bounds__(BTX * BTY, 3)
void kan_conv_kernel(const float* __restrict__ x,
                     const float* __restrict__ bw,
                     const float* __restrict__ sw,
                     float* __restrict__ out)
{
    // ---- prologue: folded polynomial coefficients per tap ----
    float c1_[9], c2_[9], c3_[9], d1_[9], d2_[9];
    float cstar = 0.0f;
#pragma unroll
    for (int p = 0; p < 9; ++p) {
        float s_[6];
#pragma unroll
        for (int k = 0; k < 6; ++k) s_[k] = __ldg(&sw[p * NB + 2 + k]);
        const float bwp = __ldg(&bw[p]);

        const float D0 = (-s_[0] + 3.0f * s_[1] - 3.0f * s_[2] + s_[3]) * (1.0f / 6.0f);
        const float D1 = (-s_[1] + 3.0f * s_[2] - 3.0f * s_[3] + s_[4]) * (1.0f / 6.0f);
        const float D2 = (-s_[2] + 3.0f * s_[3] - 3.0f * s_[4] + s_[5]) * (1.0f / 6.0f);
        const float A  = (s_[0] + 4.0f * s_[1] + s_[2]) * (1.0f / 6.0f);
        const float B  = (s_[2] - s_[0]) * 0.5f;
        const float C  = (s_[0] - 2.0f * s_[1] + s_[2]) * 0.5f;

        cstar += A + 0.5f * B + 0.25f * C + 0.125f * D0 + bwp * Q0;
        c1_[p] = 2.5f * B + 2.5f * C + 1.875f * D0 + bwp * Q1;
        c2_[p] = 6.25f * C + 9.375f * D0 + bwp * Q2;
        c3_[p] = 15.625f * D0 + bwp * Q3;
        d1_[p] = 15.625f * (D1 - D0);
        d2_[p] = 15.625f * (D2 - D1);
    }

    const int batch = blockIdx.z;
    const int oc0 = (blockIdx.x * BTX + threadIdx.x) * TW;
    const int or0 = (blockIdx.y * BTY + threadIdx.y) * TH;
    const float* __restrict__ xb = x + batch * H * W;

    float acc[TH][TW];
#pragma unroll
    for (int i = 0; i < TH; ++i)
#pragma unroll
        for (int j = 0; j < TW; ++j) acc[i][j] = cstar;

    const bool fastcols = (oc0 + TW + 2 <= W);   // vector loads fully in-row

#pragma unroll
    for (int r = 0; r < TH + 2; ++r) {
        const int ir = min(or0 + r, H - 1);
        const float* __restrict__ xrow = xb + ir * W;

        float px[TW + 2];
        if (fastcols) {
            const float4 v4 = *reinterpret_cast<const float4*>(xrow + oc0);
            const float2 v2 = *reinterpret_cast<const float2*>(xrow + oc0 + 4);
            px[0] = v4.x; px[1] = v4.y; px[2] = v4.z; px[3] = v4.w;
            px[4] = v2.x; px[5] = v2.y;
        } else {
#pragma unroll
            for (int cc = 0; cc < TW + 2; ++cc)
                px[cc] = __ldg(&xrow[min(oc0 + cc, W - 1)]);
        }

#pragma unroll
        for (int cc = 0; cc < TW + 2; ++cc) {
            const float xv = px[cc];

            // --- per-pixel features: cheap ops, no MUFU ---
            const float x2 = xv * xv;
            const float x3 = x2 * xv;
            const float r1 = fmaxf(xv - 0.2f, 0.0f);
            const float r2 = fmaxf(xv - 0.6f, 0.0f);
            const float R1 = (r1 * r1) * r1;
            const float R2 = (r2 * r2) * r2;

            // --- accumulate: 5 FFMA per (pixel, output) ---
#pragma unroll
            for (int orr = 0; orr < TH; ++orr) {
                const int a = r - orr;
                if (a < 0 || a > 2) continue;
#pragma unroll
                for (int occ = 0; occ < TW; ++occ) {
                    const int b = cc - occ;
                    if (b < 0 || b > 2) continue;
                    const int p = a * 3 + b;
                    float v = fmaf(xv, c1_[p], acc[orr][occ]);
                    v = fmaf(x2, c2_[p], v);
                    v = fmaf(x3, c3_[p], v);
                    v = fmaf(R1, d1_[p], v);
                    v = fmaf(R2, d2_[p], v);
                    acc[orr][occ] = v;
                }
            }
        }
    }

    float* __restrict__ ob = out + batch * Ho * Wo;
#pragma unroll
    for (int orr = 0; orr < TH; ++orr) {
        const int oh = or0 + orr;
        if (oh >= Ho) continue;
        if (oc0 + TW <= Wo) {
            // oh*Wo + oc0 is even (Wo=254 even, oc0 mult of 4) -> 8B aligned.
            float* rowp = ob + oh * Wo + oc0;
            *reinterpret_cast<float2*>(rowp)     = make_float2(acc[orr][0], acc[orr][1]);
            *reinterpret_cast<float2*>(rowp + 2) = make_float2(acc[orr][2], acc[orr][3]);
        } else {
#pragma unroll
            for (int occ = 0; occ < TW; ++occ) {
                const int ow = oc0 + occ;
                if (ow < Wo) ob[oh * Wo + ow] = acc[orr][occ];
            }
        }
    }
}

extern "C" void kernel_launch(void* const* d_in, const int* in_sizes, int n_in,
                              void* d_out, int out_size)
{
    const float* x  = (const float*)d_in[0];
    const float* bw = (const float*)d_in[1];
    const float* sw = (const float*)d_in[2];
    float* out = (float*)d_out;

    dim3 block(BTX, BTY);
    dim3 grid((Wo + BTX * TW - 1) / (BTX * TW),   // 2
              (Ho + BTY * TH - 1) / (BTY * TH),   // 16
              32);
    kan_conv_kernel<<<grid, block>>>(x, bw, sw, out);
}

// round 11
// speedup vs baseline: 1.1737x; 1.1737x over previous
#include <cuda_runtime.h>

// KAN 3x3 convolution — fully polynomialized, pre-folded coefficients.
// x: (32, 256, 256) f32 in [0,1), base_weight: (3,3), spline_weight: (3,3,8)
// out: (32, 254, 254) f32
//
// spline_p(x) + silu(x)*bw_p collapses (x in [0,1), silu ~ Chebyshev cubic,
// abs err ~1.3e-4) to:  c1'x + c2'x^2 + c3'x^3 + d1 R1 + d2 R2, with
// R_k = relu(x-knot_k)^3 and all constants folded into one C*.
//
// The coefficient fold runs ONCE in a tiny pre-kernel into a __device__
// buffer; the main kernel (4x4 tile, 3 CTAs/SM) just loads 46 floats.
// Keeps the 16-way per-thread amortization while gaining occupancy.

namespace {
constexpr int H  = 256, W  = 256;
constexpr int Ho = 254, Wo = 254;
constexpr int NB = 8;          // GRID_SIZE + SPLINE_ORDER
constexpr int TW = 4, TH = 4;  // per-thread output tile
constexpr int BTX = 32, BTY = 8;  // 256 threads; block covers 128x32 outputs

// Chebyshev cubic fit of silu on [0,1]
constexpr float Q0 = 0.0001204f;
constexpr float Q1 = 0.496111f;
constexpr float Q2 = 0.270337f;
constexpr float Q3 = -0.035467f;
}

// [p*5 + t], t = 0..4 -> (c1, c2, c3, d1, d2); [45] = C* (all constants).
__device__ float g_coef[46];

__global__ void fold_kernel(const float* __restrict__ bw,
                            const float* __restrict__ sw)
{
    const int p = threadIdx.x;
    if (p < 9) {
        float s_[6];
#pragma unroll
        for (int k = 0; k < 6; ++k) s_[k] = sw[p * NB + 2 + k];
        const float bwp = bw[p];

        const float D0 = (-s_[0] + 3.0f * s_[1] - 3.0f * s_[2] + s_[3]) * (1.0f / 6.0f);
        const float D1 = (-s_[1] + 3.0f * s_[2] - 3.0f * s_[3] + s_[4]) * (1.0f / 6.0f);
        const float D2 = (-s_[2] + 3.0f * s_[3] - 3.0f * s_[4] + s_[5]) * (1.0f / 6.0f);
        const float B  = (s_[2] - s_[0]) * 0.5f;
        const float C  = (s_[0] - 2.0f * s_[1] + s_[2]) * 0.5f;

        g_coef[p * 5 + 0] = 2.5f * B + 2.5f * C + 1.875f * D0 + bwp * Q1;
        g_coef[p * 5 + 1] = 6.25f * C + 9.375f * D0 + bwp * Q2;
        g_coef[p * 5 + 2] = 15.625f * D0 + bwp * Q3;
        g_coef[p * 5 + 3] = 15.625f * (D1 - D0);
        g_coef[p * 5 + 4] = 15.625f * (D2 - D1);
    }
    if (p == 0) {
        float cs = 0.0f;
        for (int q = 0; q < 9; ++q) {
            float s0 = sw[q * NB + 2], s1 = sw[q * NB + 3];
            float s2 = sw[q * NB + 4], s3 = sw[q * NB + 5];
            const float D0 = (-s0 + 3.0f * s1 - 3.0f * s2 + s3) * (1.0f / 6.0f);
            const float A  = (s0 + 4.0f * s1 + s2) * (1.0f / 6.0f);
            const float B  = (s2 - s0) * 0.5f;
            const float C  = (s0 - 2.0f * s1 + s2) * 0.5f;
            cs += A + 0.5f * B + 0.25f * C + 0.125f * D0 + bw[q] * Q0;
        }
        g_coef[45] = cs;
    }
}

__global__ __launch_bounds__(BTX * BTY, 3)
void kan_conv_kernel(const float* __restrict__ x,
                     float* __restrict__ out)
{
    // ---- prologue: 46 broadcast loads, no math ----
    float c1_[9], c2_[9], c3_[9], d1_[9], d2_[9];
#pragma unroll
    for (int p = 0; p < 9; ++p) {
        c1_[p] = __ldg(&g_coef[p * 5 + 0]);
        c2_[p] = __ldg(&g_coef[p * 5 + 1]);
        c3_[p] = __ldg(&g_coef[p * 5 + 2]);
        d1_[p] = __ldg(&g_coef[p * 5 + 3]);
        d2_[p] = __ldg(&g_coef[p * 5 + 4]);
    }
    const float cstar = __ldg(&g_coef[45]);

    const int batch = blockIdx.z;
    const int oc0 = (blockIdx.x * BTX + threadIdx.x) * TW;
    const int or0 = (blockIdx.y * BTY + threadIdx.y) * TH;
    const float* __restrict__ xb = x + batch * H * W;

    float acc[TH][TW];
#pragma unroll
    for (int i = 0; i < TH; ++i)
#pragma unroll
        for (int j = 0; j < TW; ++j) acc[i][j] = cstar;

    const bool fastcols = (oc0 + TW + 2 <= W);   // vector loads fully in-row

#pragma unroll
    for (int r = 0; r < TH + 2; ++r) {
        const int ir = min(or0 + r, H - 1);
        const float* __restrict__ xrow = xb + ir * W;

        float px[TW + 2];
        if (fastcols) {
            const float4 v4 = *reinterpret_cast<const float4*>(xrow + oc0);
            const float2 v2 = *reinterpret_cast<const float2*>(xrow + oc0 + 4);
            px[0] = v4.x; px[1] = v4.y; px[2] = v4.z; px[3] = v4.w;
            px[4] = v2.x; px[5] = v2.y;
        } else {
#pragma unroll
            for (int cc = 0; cc < TW + 2; ++cc)
                px[cc] = __ldg(&xrow[min(oc0 + cc, W - 1)]);
        }

#pragma unroll
        for (int cc = 0; cc < TW + 2; ++cc) {
            const float xv = px[cc];

            // --- per-pixel features: cheap ops, no MUFU ---
            const float x2 = xv * xv;
            const float x3 = x2 * xv;
            const float r1 = fmaxf(xv - 0.2f, 0.0f);
            const float r2 = fmaxf(xv - 0.6f, 0.0f);
            const float R1 = (r1 * r1) * r1;
            const float R2 = (r2 * r2) * r2;

            // --- accumulate: 5 FFMA per (pixel, output) ---
#pragma unroll
            for (int orr = 0; orr < TH; ++orr) {
                const int a = r - orr;
                if (a < 0 || a > 2) continue;
#pragma unroll
                for (int occ = 0; occ < TW; ++occ) {
                    const int b = cc - occ;
                    if (b < 0 || b > 2) continue;
                    const int p = a * 3 + b;
                    float v = fmaf(xv, c1_[p], acc[orr][occ]);
                    v = fmaf(x2, c2_[p], v);
                    v = fmaf(x3, c3_[p], v);
                    v = fmaf(R1, d1_[p], v);
                    v = fmaf(R2, d2_[p], v);
                    acc[orr][occ] = v;
                }
            }
        }
    }

    float* __restrict__ ob = out + batch * Ho * Wo;
#pragma unroll
    for (int orr = 0; orr < TH; ++orr) {
        const int oh = or0 + orr;
        if (oh >= Ho) continue;
        if (oc0 + TW <= Wo) {
            // oh*Wo + oc0 is even (Wo=254 even, oc0 mult of 4) -> 8B aligned.
            float* rowp = ob + oh * Wo + oc0;
            *reinterpret_cast<float2*>(rowp)     = make_float2(acc[orr][0], acc[orr][1]);
            *reinterpret_cast<float2*>(rowp + 2) = make_float2(acc[orr][2], acc[orr][3]);
        } else {
#pragma unroll
            for (int occ = 0; occ < TW; ++occ) {
                const int ow = oc0 + occ;
                if (ow < Wo) ob[oh * Wo + ow] = acc[orr][occ];
            }
        }
    }
}

extern "C" void kernel_launch(void* const* d_in, const int* in_sizes, int n_in,
                              void* d_out, int out_size)
{
    const float* x  = (const float*)d_in[0];
    const float* bw = (const float*)d_in[1];
    const float* sw = (const float*)d_in[2];
    float* out = (float*)d_out;

    fold_kernel<<<1, 32>>>(bw, sw);

    dim3 block(BTX, BTY);
    dim3 grid((Wo + BTX * TW - 1) / (BTX * TW),   // 2
              (Ho + BTY * TH - 1) / (BTY * TH),   // 8
              32);
    kan_conv_kernel<<<grid, block>>>(x, out);
}